// round 1
// baseline (speedup 1.0000x reference)
#include <cuda_runtime.h>
#include <stdint.h>

// ---------------- problem constants ----------------
#define MAXM      300000
#define NCLS      80
#define TOPK      1000
#define CONF      0.001f
#define NMSTH     0.5f
#define CLSOFF    4096.0f
#define CAND_CAP  4096
#define SUPW      32        // 32 x u32 words = 1024 bits >= TOPK
#define NBINS     4096

// ---------------- device scratch (no allocations allowed) ----------------
__device__ uint32_t g_scorebits[MAXM];
__device__ int32_t  g_label[MAXM];
__device__ uint32_t g_hist[NBINS];
__device__ uint32_t g_prefix;
__device__ uint32_t g_prefix_mask;
__device__ uint32_t g_need;
__device__ uint32_t g_cand_cnt;
__device__ unsigned long long g_cand[CAND_CAP];
__device__ float    g_tk_score[TOPK];
__device__ int32_t  g_tk_label[TOPK];
__device__ float    g_tk_box[TOPK * 4];
__device__ uint32_t g_sup[TOPK * SUPW];

__device__ __forceinline__ float sigf(float x) {
    return 1.0f / (1.0f + expf(-x));
}

// ---------------- init: zero hist + state ----------------
__global__ void k_init() {
    int t = blockIdx.x * blockDim.x + threadIdx.x;
    if (t < NBINS) g_hist[t] = 0;
    if (t == 0) {
        g_prefix      = 0u;
        g_prefix_mask = 0u;
        g_need        = TOPK;
        g_cand_cnt    = 0u;
    }
}

// ---------------- pass 1: fused score + argmax label + round-0 histogram ----------------
__global__ void k_score(const float* __restrict__ obj,
                        const float* __restrict__ cls, int M) {
    __shared__ uint32_t sh[NBINS];
    for (int i = threadIdx.x; i < NBINS; i += blockDim.x) sh[i] = 0;
    __syncthreads();

    int m = blockIdx.x * blockDim.x + threadIdx.x;
    if (m < M) {
        float so = sigf(obj[m]);
        const float4* c4 = (const float4*)(cls + (size_t)m * NCLS);
        float best = -1.0f;
        int lab = 0;
#pragma unroll
        for (int q = 0; q < NCLS / 4; q++) {
            float4 v = c4[q];
            float f;
            f = sqrtf(so * sigf(v.x)); if (f > best) { best = f; lab = q * 4 + 0; }
            f = sqrtf(so * sigf(v.y)); if (f > best) { best = f; lab = q * 4 + 1; }
            f = sqrtf(so * sigf(v.z)); if (f > best) { best = f; lab = q * 4 + 2; }
            f = sqrtf(so * sigf(v.w)); if (f > best) { best = f; lab = q * 4 + 3; }
        }
        uint32_t bits = __float_as_uint(best);  // positive float: uint order == float order
        g_scorebits[m] = bits;
        g_label[m] = lab;
        atomicAdd(&sh[bits >> 20], 1u);
    }
    __syncthreads();
    for (int i = threadIdx.x; i < NBINS; i += blockDim.x) {
        uint32_t v = sh[i];
        if (v) atomicAdd(&g_hist[i], v);
    }
}

// ---------------- refinement histogram rounds (shift = 8, then 0) ----------------
__global__ void k_hist(int shift, uint32_t fmask, int M) {
    __shared__ uint32_t sh[NBINS];
    for (int i = threadIdx.x; i < NBINS; i += blockDim.x) sh[i] = 0;
    __syncthreads();
    uint32_t pre = g_prefix, pmask = g_prefix_mask;
    for (int m = blockIdx.x * blockDim.x + threadIdx.x; m < M;
         m += gridDim.x * blockDim.x) {
        uint32_t b = g_scorebits[m];
        if ((b & pmask) == pre) atomicAdd(&sh[(b >> shift) & fmask], 1u);
    }
    __syncthreads();
    for (int i = threadIdx.x; i < NBINS; i += blockDim.x) {
        uint32_t v = sh[i];
        if (v) atomicAdd(&g_hist[i], v);
    }
}

// ---------------- select bin holding the k-th largest; zero hist for next round ----------------
__global__ void k_select(int shift, uint32_t fmask) {
    __shared__ uint32_t ssum[1024];
    int t = threadIdx.x;
    uint32_t h0 = g_hist[t * 4 + 0];
    uint32_t h1 = g_hist[t * 4 + 1];
    uint32_t h2 = g_hist[t * 4 + 2];
    uint32_t h3 = g_hist[t * 4 + 3];
    ssum[t] = h0 + h1 + h2 + h3;
    uint32_t need = g_need;
    __syncthreads();  // also guarantees all hist reads complete before the zeroing below
    // inclusive suffix scan across the 1024 chunk sums
    for (int off = 1; off < 1024; off <<= 1) {
        uint32_t v = (t + off < 1024) ? ssum[t + off] : 0u;
        __syncthreads();
        ssum[t] += v;
        __syncthreads();
    }
    uint32_t cum = (t < 1023) ? ssum[t + 1] : 0u;  // count strictly above my chunk
    uint32_t hh[4] = {h0, h1, h2, h3};
#pragma unroll
    for (int c = 3; c >= 0; c--) {
        uint32_t bc = hh[c];
        if (bc > 0 && cum < need && cum + bc >= need) {
            uint32_t bin = (uint32_t)(t * 4 + c);
            g_prefix      = g_prefix | (bin << shift);
            g_prefix_mask = g_prefix_mask | (fmask << shift);
            g_need        = need - cum;   // how many still needed from == this bin
        }
        cum += bc;
    }
    // zero histogram for the next round
    g_hist[t * 4 + 0] = 0;
    g_hist[t * 4 + 1] = 0;
    g_hist[t * 4 + 2] = 0;
    g_hist[t * 4 + 3] = 0;
}

// ---------------- gather all candidates with bits >= threshold ----------------
__global__ void k_gather(int M) {
    uint32_t T = g_prefix;  // after 3 rounds this is the exact 1000th score bit pattern
    for (int m = blockIdx.x * blockDim.x + threadIdx.x; m < M;
         m += gridDim.x * blockDim.x) {
        uint32_t b = g_scorebits[m];
        if (b >= T) {
            uint32_t p = atomicAdd(&g_cand_cnt, 1u);
            if (p < CAND_CAP) {
                // key: (score_bits << 32) | (~index) -> descending sort gives
                // score desc, ties -> lower index first (jax top_k semantics)
                g_cand[p] = ((unsigned long long)b << 32) |
                            (unsigned long long)(0xFFFFFFFFu - (uint32_t)m);
            }
        }
    }
}

// ---------------- bitonic sort candidates, emit top-1000 (score, label, box) ----------------
__global__ void k_sortmk(const float* __restrict__ boxp) {
    __shared__ unsigned long long sh[CAND_CAP];
    int t = threadIdx.x;
    uint32_t n = g_cand_cnt;
    if (n > CAND_CAP) n = CAND_CAP;
    for (int i = t; i < CAND_CAP; i += 1024) {
        unsigned long long raw = (i < (int)n) ? g_cand[i] : 0ull;
        sh[i] = ~raw;  // ascending sort of ~key == descending sort of key; pads go last
    }
    __syncthreads();
    for (int k = 2; k <= CAND_CAP; k <<= 1) {
        for (int j = k >> 1; j > 0; j >>= 1) {
            for (int i = t; i < CAND_CAP; i += 1024) {
                int ixj = i ^ j;
                if (ixj > i) {
                    unsigned long long a = sh[i], b = sh[ixj];
                    bool up = ((i & k) == 0);
                    if ((a > b) == up) { sh[i] = b; sh[ixj] = a; }
                }
            }
            __syncthreads();
        }
    }
    if (t < TOPK) {
        unsigned long long raw = ~sh[t];
        uint32_t bits = (uint32_t)(raw >> 32);
        uint32_t idx  = 0xFFFFFFFFu - (uint32_t)(raw & 0xFFFFFFFFull);
        g_tk_score[t] = __uint_as_float(bits);
        g_tk_label[t] = g_label[idx];
        float4 bx = ((const float4*)boxp)[idx];
        ((float4*)g_tk_box)[t] = bx;
    }
}

// ---------------- precompute suppression bit-matrix (iou > 0.5, j < i) ----------------
__global__ void k_sup() {
    int p = blockIdx.x * blockDim.x + threadIdx.x;
    if (p >= TOPK * SUPW) return;
    int i = p >> 5;
    int w = p & 31;
    int jbase = w * 32;
    uint32_t bits = 0;
    if (jbase < i) {
        float offi = (float)g_tk_label[i] * CLSOFF;
        float ix1 = g_tk_box[i * 4 + 0] + offi;
        float iy1 = g_tk_box[i * 4 + 1] + offi;
        float ix2 = g_tk_box[i * 4 + 2] + offi;
        float iy2 = g_tk_box[i * 4 + 3] + offi;
        float ia = fmaxf(ix2 - ix1, 0.0f) * fmaxf(iy2 - iy1, 0.0f);
        int jend = jbase + 32; if (jend > i) jend = i;
        for (int j = jbase; j < jend; j++) {
            float offj = (float)g_tk_label[j] * CLSOFF;
            float jx1 = g_tk_box[j * 4 + 0] + offj;
            float jy1 = g_tk_box[j * 4 + 1] + offj;
            float jx2 = g_tk_box[j * 4 + 2] + offj;
            float jy2 = g_tk_box[j * 4 + 3] + offj;
            float ja = fmaxf(jx2 - jx1, 0.0f) * fmaxf(jy2 - jy1, 0.0f);
            float xx1 = fmaxf(ix1, jx1);
            float yy1 = fmaxf(iy1, jy1);
            float xx2 = fminf(ix2, jx2);
            float yy2 = fminf(iy2, jy2);
            float inter = fmaxf(xx2 - xx1, 0.0f) * fmaxf(yy2 - yy1, 0.0f);
            float iou = inter / (ia + ja - inter + 1e-9f);
            if (iou > NMSTH) bits |= (1u << (j - jbase));
        }
    }
    g_sup[p] = bits;
}

// ---------------- serial greedy NMS sweep + output write ----------------
extern __shared__ uint32_t sh_sup[];  // TOPK*SUPW u32 = 128000 B

__global__ void k_nms(float* __restrict__ out, int out_size) {
    int t = threadIdx.x;
    for (int i = t; i < TOPK * SUPW; i += blockDim.x) sh_sup[i] = g_sup[i];
    __shared__ uint32_t keepsh[SUPW];
    if (t < SUPW) {
        uint32_t kw = 0;
        for (int b = 0; b < 32; b++) {
            int j = t * 32 + b;
            if (j < TOPK && g_tk_score[j] > CONF) kw |= (1u << b);
        }
        keepsh[t] = kw;
    }
    __syncthreads();
    if (t < 32) {  // warp 0: serial sweep, lane t owns keep word t
        uint32_t keepw = keepsh[t];
        for (int i = 0; i < TOPK; i++) {
            int iw = i >> 5;
            uint32_t ib = (uint32_t)(i & 31);
            uint32_t lt = (t < iw) ? 0xFFFFFFFFu
                        : ((t == iw) ? ((1u << ib) - 1u) : 0u);
            uint32_t v = sh_sup[i * 32 + t] & keepw & lt;
            bool any = __any_sync(0xFFFFFFFFu, v != 0u);
            if (any && t == iw) keepw &= ~(1u << ib);
        }
        keepsh[t] = keepw;
    }
    __syncthreads();
    if (t < TOPK) {
        float kf = ((keepsh[t >> 5] >> (t & 31)) & 1u) ? 1.0f : 0.0f;
        float s = g_tk_score[t];
        out[t * 5 + 0] = s * kf;
        out[t * 5 + 1] = g_tk_box[t * 4 + 0] * kf;
        out[t * 5 + 2] = g_tk_box[t * 4 + 1] * kf;
        out[t * 5 + 3] = g_tk_box[t * 4 + 2] * kf;
        out[t * 5 + 4] = g_tk_box[t * 4 + 3] * kf;
        if (out_size >= 6000) out[5000 + t] = (float)g_tk_label[t];
        if (out_size >= 7000) out[6000 + t] = kf;
    }
}

// ---------------- launch ----------------
extern "C" void kernel_launch(void* const* d_in, const int* in_sizes, int n_in,
                              void* d_out, int out_size) {
    const float* obj  = (const float*)d_in[0];
    const float* cls  = (const float*)d_in[1];
    const float* boxp = (const float*)d_in[2];
    float* out = (float*)d_out;
    int M = in_sizes[0];
    if (M > MAXM) M = MAXM;

    (void)n_in;
    cudaFuncSetAttribute(k_nms, cudaFuncAttributeMaxDynamicSharedMemorySize,
                         TOPK * SUPW * (int)sizeof(uint32_t));

    int gs = (M + 255) / 256;
    k_init<<<(NBINS + 255) / 256, 256>>>();
    k_score<<<gs, 256>>>(obj, cls, M);
    k_select<<<1, 1024>>>(20, 0xFFFu);
    k_hist<<<gs, 256>>>(8, 0xFFFu, M);
    k_select<<<1, 1024>>>(8, 0xFFFu);
    k_hist<<<gs, 256>>>(0, 0xFFu, M);
    k_select<<<1, 1024>>>(0, 0xFFu);
    k_gather<<<gs, 256>>>(M);
    k_sortmk<<<1, 1024>>>(boxp);
    k_sup<<<(TOPK * SUPW + 255) / 256, 256>>>();
    k_nms<<<1, 1024, TOPK * SUPW * (int)sizeof(uint32_t)>>>(out, out_size);
}